// round 1
// baseline (speedup 1.0000x reference)
#include <cuda_runtime.h>
#include <cuda_bf16.h>
#include <math.h>

// Problem constants (fixed-shape problem)
#define NN 50000
#define NE 800000
// fin is always 128 (IN=128, H*D=128). HF (=H*fout) is 128,128,160. FOUT is 32,32,40.

// ---------------- scratch (device globals; no allocation allowed) ----------------
__device__ float g_z[NN * 160];     // z = x @ Wc      [N, HF]
__device__ float g_lin[NN * 160];   // lin = x @ Wl    [N, HF]
__device__ float g_x[NN * 128];     // layer input buffer (BN output)
__device__ float g_h[NN * 160];     // layer output (pre-BN / pre-headmean)
__device__ float g_el[NN * 4];      // [N, H]
__device__ float g_er[NN * 4];      // [N, H]
__device__ int   g_rowptr[NN + 1];
__device__ int   g_cursor[NN];
__device__ int   g_cnt[NN];
__device__ int   g_colsrc[NE];      // CSR col: src node per (dst-sorted) edge
__device__ float g_stat[320];       // BN column sums [0,128) and sumsq [128,256)

// ---------------- CSR build ----------------
__global__ void k_zero_cnt() {
    int i = blockIdx.x * blockDim.x + threadIdx.x;
    if (i < NN) g_cnt[i] = 0;
}

__global__ void k_hist(const int* __restrict__ dst) {
    int e = blockIdx.x * blockDim.x + threadIdx.x;
    if (e < NE) atomicAdd(&g_cnt[dst[e]], 1);
}

// single-block exclusive scan of g_cnt -> g_rowptr (chunked, 1024 threads)
__global__ void k_scan() {
    __shared__ int sm[1024];
    const int CH = 49;  // 1024*49 = 50176 >= NN
    int t = threadIdx.x;
    int base = t * CH;
    int s = 0;
    for (int i = 0; i < CH; i++) {
        int idx = base + i;
        if (idx < NN) s += g_cnt[idx];
    }
    sm[t] = s;
    __syncthreads();
    // Hillis-Steele inclusive scan
    for (int d = 1; d < 1024; d <<= 1) {
        int add = (t >= d) ? sm[t - d] : 0;
        __syncthreads();
        sm[t] += add;
        __syncthreads();
    }
    int excl = sm[t] - s;
    int run = excl;
    for (int i = 0; i < CH; i++) {
        int idx = base + i;
        if (idx < NN) {
            g_rowptr[idx] = run;
            run += g_cnt[idx];
        }
    }
    if (t == 1023) g_rowptr[NN] = sm[1023];
}

__global__ void k_copycur() {
    int i = blockIdx.x * blockDim.x + threadIdx.x;
    if (i < NN) g_cursor[i] = g_rowptr[i];
}

__global__ void k_scatter(const int* __restrict__ src, const int* __restrict__ dst) {
    int e = blockIdx.x * blockDim.x + threadIdx.x;
    if (e < NE) {
        int p = atomicAdd(&g_cursor[dst[e]], 1);
        g_colsrc[p] = src[e];
    }
}

// ---------------- dual GEMM: z = x@Wc, lin = x@Wl  (fin=128 always) ----------------
// block: 32 rows x (2*HF) threads; thread t<HF -> Wc col t, else Wl col t-HF
template <int HF>
__global__ __launch_bounds__(2 * HF) void k_gemm(const float* __restrict__ x,
                                                 const float* __restrict__ Wc,
                                                 const float* __restrict__ Wl) {
    __shared__ float xs[32][36];  // 144B row stride keeps float4 alignment
    int row0 = blockIdx.x * 32;
    int t = threadIdx.x;
    bool isC = (t < HF);
    const float* W = isC ? Wc : Wl;
    int col = isC ? t : (t - HF);

    float acc[32];
#pragma unroll
    for (int r = 0; r < 32; r++) acc[r] = 0.f;

    for (int k0 = 0; k0 < 128; k0 += 32) {
        for (int i = t; i < 1024; i += 2 * HF) {
            int r = i >> 5, kk = i & 31;
            int row = row0 + r;
            xs[r][kk] = (row < NN) ? x[row * 128 + k0 + kk] : 0.f;
        }
        __syncthreads();
        float w[32];
#pragma unroll
        for (int kk = 0; kk < 32; kk++) w[kk] = W[(k0 + kk) * HF + col];
#pragma unroll
        for (int r = 0; r < 32; r++) {
#pragma unroll
            for (int kk = 0; kk < 32; kk += 4) {
                float4 xv = *(const float4*)&xs[r][kk];
                acc[r] = fmaf(xv.x, w[kk + 0], acc[r]);
                acc[r] = fmaf(xv.y, w[kk + 1], acc[r]);
                acc[r] = fmaf(xv.z, w[kk + 2], acc[r]);
                acc[r] = fmaf(xv.w, w[kk + 3], acc[r]);
            }
        }
        __syncthreads();
    }
    float* o = isC ? g_z : g_lin;
#pragma unroll
    for (int r = 0; r < 32; r++) {
        int row = row0 + r;
        if (row < NN) o[row * HF + col] = acc[r];
    }
}

// ---------------- el/er projections ----------------
template <int HF, int FOUT>
__global__ void k_elr(const float* __restrict__ al, const float* __restrict__ ar) {
    int idx = blockIdx.x * blockDim.x + threadIdx.x;
    if (idx >= NN * 4) return;
    int n = idx >> 2, h = idx & 3;
    const float* zp = g_z + n * HF + h * FOUT;
    float sl = 0.f, sr = 0.f;
#pragma unroll 8
    for (int d = 0; d < FOUT; d++) {
        float v = zp[d];
        sl = fmaf(v, __ldg(al + h * FOUT + d), sl);
        sr = fmaf(v, __ldg(ar + h * FOUT + d), sr);
    }
    g_el[idx] = sl;
    g_er[idx] = sr;
}

// ---------------- edge softmax + aggregation (CSR, one warp per dst node) ----------
template <int HF, int FOUT>
__global__ __launch_bounds__(256) void k_agg(const float* __restrict__ bc) {
    const unsigned FULL = 0xffffffffu;
    int warp = (blockIdx.x * 256 + threadIdx.x) >> 5;
    int lane = threadIdx.x & 31;
    if (warp >= NN) return;
    int n = warp;
    int beg = g_rowptr[n], end = g_rowptr[n + 1];

    float er_h = (lane < 4) ? g_er[n * 4 + lane] : 0.f;
    float er0 = __shfl_sync(FULL, er_h, 0);
    float er1 = __shfl_sync(FULL, er_h, 1);
    float er2 = __shfl_sync(FULL, er_h, 2);
    float er3 = __shfl_sync(FULL, er_h, 3);

    // pass 1: per-head max over incoming edges (lanes parallel over edges)
    float mx0 = -1e30f, mx1 = -1e30f, mx2 = -1e30f, mx3 = -1e30f;
    for (int e = beg + lane; e < end; e += 32) {
        int s = g_colsrc[e];
        float4 ev = *(const float4*)(g_el + 4 * s);
        float a;
        a = ev.x + er0; a = a > 0.f ? a : 0.2f * a; mx0 = fmaxf(mx0, a);
        a = ev.y + er1; a = a > 0.f ? a : 0.2f * a; mx1 = fmaxf(mx1, a);
        a = ev.z + er2; a = a > 0.f ? a : 0.2f * a; mx2 = fmaxf(mx2, a);
        a = ev.w + er3; a = a > 0.f ? a : 0.2f * a; mx3 = fmaxf(mx3, a);
    }
#pragma unroll
    for (int o = 16; o; o >>= 1) {
        mx0 = fmaxf(mx0, __shfl_xor_sync(FULL, mx0, o));
        mx1 = fmaxf(mx1, __shfl_xor_sync(FULL, mx1, o));
        mx2 = fmaxf(mx2, __shfl_xor_sync(FULL, mx2, o));
        mx3 = fmaxf(mx3, __shfl_xor_sync(FULL, mx3, o));
    }
    float m_l = (lane == 0) ? mx0 : (lane == 1) ? mx1 : (lane == 2) ? mx2 : mx3;

    constexpr int J = HF / 32;
    float acc[J];
    int hj[J];
#pragma unroll
    for (int j = 0; j < J; j++) {
        acc[j] = 0.f;
        hj[j] = (lane + 32 * j) / FOUT;
    }

    // pass 2: accumulate unnormalized weighted sum + softmax denominator
    float sh = 0.f;
    for (int base = beg; base < end; base += 32) {
        int mye = base + lane;
        int mys = (mye < end) ? g_colsrc[mye] : 0;
        int cnt = min(32, end - base);
        for (int i = 0; i < cnt; i++) {
            int s = __shfl_sync(FULL, mys, i);
            float ext = 0.f;
            if (lane < 4) {
                float ee = g_el[4 * s + lane] + er_h;
                ee = ee > 0.f ? ee : 0.2f * ee;
                ext = __expf(ee - m_l);
            }
            sh += ext;
            float ex0 = __shfl_sync(FULL, ext, 0);
            float ex1 = __shfl_sync(FULL, ext, 1);
            float ex2 = __shfl_sync(FULL, ext, 2);
            float ex3 = __shfl_sync(FULL, ext, 3);
            const float* zp = g_z + s * HF;
#pragma unroll
            for (int j = 0; j < J; j++) {
                float exv;
                if (FOUT == 32)
                    exv = (j == 0) ? ex0 : (j == 1) ? ex1 : (j == 2) ? ex2 : ex3;
                else
                    exv = (hj[j] == 0) ? ex0 : (hj[j] == 1) ? ex1 : (hj[j] == 2) ? ex2 : ex3;
                acc[j] = fmaf(exv, zp[lane + 32 * j], acc[j]);
            }
        }
    }

    float s0 = __shfl_sync(FULL, sh, 0);
    float s1 = __shfl_sync(FULL, sh, 1);
    float s2 = __shfl_sync(FULL, sh, 2);
    float s3 = __shfl_sync(FULL, sh, 3);
    float r0 = 1.f / (s0 == 0.f ? 1.f : s0);
    float r1 = 1.f / (s1 == 0.f ? 1.f : s1);
    float r2 = 1.f / (s2 == 0.f ? 1.f : s2);
    float r3 = 1.f / (s3 == 0.f ? 1.f : s3);

#pragma unroll
    for (int j = 0; j < J; j++) {
        float rv;
        if (FOUT == 32)
            rv = (j == 0) ? r0 : (j == 1) ? r1 : (j == 2) ? r2 : r3;
        else
            rv = (hj[j] == 0) ? r0 : (hj[j] == 1) ? r1 : (hj[j] == 2) ? r2 : r3;
        int c = lane + 32 * j;
        g_h[n * HF + c] = acc[j] * rv + __ldg(bc + c) + g_lin[n * HF + c];
    }
}

// ---------------- BatchNorm (over rows) + ReLU ----------------
__global__ void k_zstat() {
    int i = blockIdx.x * blockDim.x + threadIdx.x;
    if (i < 320) g_stat[i] = 0.f;
}

__global__ void k_bnstats() {  // blockDim = 128 (one thread per column)
    int c = threadIdx.x;
    int G = gridDim.x;
    int per = (NN + G - 1) / G;
    int r0 = blockIdx.x * per;
    int r1 = min(NN, r0 + per);
    float s = 0.f, q = 0.f;
    for (int r = r0; r < r1; r++) {
        float v = g_h[r * 128 + c];
        s += v;
        q = fmaf(v, v, q);
    }
    atomicAdd(&g_stat[c], s);
    atomicAdd(&g_stat[128 + c], q);
}

__global__ void k_bnapply(const float* __restrict__ g, const float* __restrict__ b) {
    int idx = blockIdx.x * blockDim.x + threadIdx.x;
    if (idx >= NN * 128) return;
    int c = idx & 127;
    float mu = g_stat[c] * (1.f / NN);
    float var = g_stat[128 + c] * (1.f / NN) - mu * mu;
    float y = (g_h[idx] - mu) * rsqrtf(var + 1e-5f) * __ldg(g + c) + __ldg(b + c);
    g_x[idx] = fmaxf(y, 0.f);
}

// ---------------- final head-mean + bias ----------------
__global__ void k_headmean(const float* __restrict__ bias, float* __restrict__ out) {
    int idx = blockIdx.x * blockDim.x + threadIdx.x;
    if (idx >= NN * 40) return;
    int n = idx / 40;
    int c = idx - 40 * n;
    const float* hp = g_h + n * 160;
    float s = hp[c] + hp[40 + c] + hp[80 + c] + hp[120 + c];
    out[idx] = s * 0.25f + __ldg(bias + c);
}

// ---------------- host launch ----------------
extern "C" void kernel_launch(void* const* d_in, const int* in_sizes, int n_in,
                              void* d_out, int out_size) {
    const float* feat = (const float*)d_in[0];
    const int* src = (const int*)d_in[1];
    const int* dstp = (const int*)d_in[2];
    const float* Wc0 = (const float*)d_in[3];
    const float* al0 = (const float*)d_in[4];
    const float* ar0 = (const float*)d_in[5];
    const float* bc0 = (const float*)d_in[6];
    const float* Wl0 = (const float*)d_in[7];
    const float* Wc1 = (const float*)d_in[8];
    const float* al1 = (const float*)d_in[9];
    const float* ar1 = (const float*)d_in[10];
    const float* bc1 = (const float*)d_in[11];
    const float* Wl1 = (const float*)d_in[12];
    const float* Wc2 = (const float*)d_in[13];
    const float* al2 = (const float*)d_in[14];
    const float* ar2 = (const float*)d_in[15];
    const float* bc2 = (const float*)d_in[16];
    const float* Wl2 = (const float*)d_in[17];
    const float* g0 = (const float*)d_in[18];
    const float* b0 = (const float*)d_in[19];
    const float* g1 = (const float*)d_in[20];
    const float* b1 = (const float*)d_in[21];
    const float* bias_last = (const float*)d_in[22];
    float* out = (float*)d_out;

    float* xptr = nullptr;
    cudaGetSymbolAddress((void**)&xptr, g_x);

    // CSR build (dst-sorted)
    k_zero_cnt<<<(NN + 255) / 256, 256>>>();
    k_hist<<<(NE + 255) / 256, 256>>>(dstp);
    k_scan<<<1, 1024>>>();
    k_copycur<<<(NN + 255) / 256, 256>>>();
    k_scatter<<<(NE + 255) / 256, 256>>>(src, dstp);

    const int GB = (NN + 31) / 32;      // gemm blocks
    const int AB = (NN + 7) / 8;        // agg blocks (8 warps/block)

    // ---- layer 0 ----
    k_gemm<128><<<GB, 256>>>(feat, Wc0, Wl0);
    k_elr<128, 32><<<(NN * 4 + 127) / 128, 128>>>(al0, ar0);
    k_agg<128, 32><<<AB, 256>>>(bc0);
    k_zstat<<<2, 256>>>();
    k_bnstats<<<128, 128>>>();
    k_bnapply<<<(NN * 128 + 255) / 256, 256>>>(g0, b0);

    // ---- layer 1 ----
    k_gemm<128><<<GB, 256>>>(xptr, Wc1, Wl1);
    k_elr<128, 32><<<(NN * 4 + 127) / 128, 128>>>(al1, ar1);
    k_agg<128, 32><<<AB, 256>>>(bc1);
    k_zstat<<<2, 256>>>();
    k_bnstats<<<128, 128>>>();
    k_bnapply<<<(NN * 128 + 255) / 256, 256>>>(g1, b1);

    // ---- layer 2 ----
    k_gemm<160><<<GB, 320>>>(xptr, Wc2, Wl2);
    k_elr<160, 40><<<(NN * 4 + 127) / 128, 128>>>(al2, ar2);
    k_agg<160, 40><<<AB, 256>>>(bc2);
    k_headmean<<<(NN * 40 + 255) / 256, 256>>>(bias_last, out);
}

// round 7
// speedup vs baseline: 1.4222x; 1.4222x over previous
#include <cuda_runtime.h>
#include <cuda_bf16.h>
#include <math.h>
#include <stdint.h>

// Problem constants (fixed-shape problem)
#define NN 50000
#define NE 800000
// fin=128 always. HF (=H*fout) is 128,128,160. FOUT is 32,32,40.

// ---------------- scratch (device globals; no allocation allowed) ----------------
__device__ float g_z[NN * 160];     // z = x @ Wc      [N, HF]
__device__ float g_lin[NN * 160];   // lin = x @ Wl    [N, HF]
__device__ float g_x[NN * 128];     // layer input buffer (BN output)
__device__ float g_h[NN * 160];     // layer output (pre-BN / pre-headmean)
__device__ float g_el[NN * 4];      // [N, H]
__device__ float g_er[NN * 4];      // [N, H]
__device__ int   g_rowptr[NN + 1];
__device__ int   g_cursor[NN];
__device__ int   g_cnt[NN];
__device__ int   g_colsrc[NE];      // CSR col: src node per (dst-sorted) edge
__device__ float g_stat[320];       // BN column sums [0,128) and sumsq [128,256)

// ---------------- CSR build ----------------
__global__ void k_zero_cnt() {
    int i = blockIdx.x * blockDim.x + threadIdx.x;
    if (i < NN) g_cnt[i] = 0;
}

__global__ void k_hist(const int* __restrict__ dst) {
    int e = blockIdx.x * blockDim.x + threadIdx.x;
    if (e < NE) atomicAdd(&g_cnt[dst[e]], 1);
}

// single-block exclusive scan of g_cnt -> g_rowptr (+ cursor copy)
__global__ void k_scan() {
    __shared__ int sm[1024];
    const int CH = 49;  // 1024*49 >= NN
    int t = threadIdx.x;
    int base = t * CH;
    int s = 0;
    for (int i = 0; i < CH; i++) {
        int idx = base + i;
        if (idx < NN) s += g_cnt[idx];
    }
    sm[t] = s;
    __syncthreads();
    for (int d = 1; d < 1024; d <<= 1) {
        int add = (t >= d) ? sm[t - d] : 0;
        __syncthreads();
        sm[t] += add;
        __syncthreads();
    }
    int run = sm[t] - s;
    for (int i = 0; i < CH; i++) {
        int idx = base + i;
        if (idx < NN) {
            g_rowptr[idx] = run;
            g_cursor[idx] = run;
            run += g_cnt[idx];
        }
    }
    if (t == 1023) g_rowptr[NN] = sm[1023];
}

__global__ void k_scatter(const int* __restrict__ src, const int* __restrict__ dst) {
    int e = blockIdx.x * blockDim.x + threadIdx.x;
    if (e < NE) {
        int p = atomicAdd(&g_cursor[dst[e]], 1);
        g_colsrc[p] = src[e];
    }
}

// ================= tf32 mma.sync GEMM =================
__device__ __forceinline__ uint32_t f2tf32(float f) {
    uint32_t r;
    asm("cvt.rna.tf32.f32 %0, %1;" : "=r"(r) : "f"(f));
    return r;
}
__device__ __forceinline__ void mma_tf32(float* c, const uint32_t* a, const uint32_t* b) {
    asm volatile(
        "mma.sync.aligned.m16n8k8.row.col.f32.tf32.tf32.f32 "
        "{%0,%1,%2,%3}, {%4,%5,%6,%7}, {%8,%9}, {%0,%1,%2,%3};\n"
        : "+f"(c[0]), "+f"(c[1]), "+f"(c[2]), "+f"(c[3])
        : "r"(a[0]), "r"(a[1]), "r"(a[2]), "r"(a[3]), "r"(b[0]), "r"(b[1]));
}

// One CTA: 128-row tile x HF cols. blockIdx.y: 0 -> z=x@Wc, 1 -> lin=x@Wl.
// A [128x128] and W [128xHF] staged in smem (tf32-rounded, pad=4 words -> bank-clean).
// Warp tile 32x32 (2 m-tiles x 4 n-tiles of m16n8k8). Warp grid: 4 rows x HF/32 cols.
template <int HF>
__global__ __launch_bounds__(4 * (HF / 32) * 32, 1)
void k_gemm_mma(const float* __restrict__ x, const float* __restrict__ Wc,
                const float* __restrict__ Wl) {
    constexpr int NCW = HF / 32;        // col-warps
    constexpr int NT = 4 * NCW * 32;    // threads (512 / 640)
    constexpr int SA = 132;             // A smem row stride (words)
    constexpr int SB = HF + 4;          // B smem row stride (words)
    extern __shared__ uint32_t smw[];
    uint32_t* As = smw;                 // [128][SA]
    uint32_t* Bs = smw + 128 * SA;      // [128][SB]

    const float* W = blockIdx.y ? Wl : Wc;
    float* O = blockIdx.y ? g_lin : g_z;
    int tid = threadIdx.x;
    int row0g = blockIdx.x * 128;

    // stage A (guarded, tf32-rounded)
    for (int i = tid; i < 128 * 32; i += NT) {
        int row = i >> 5, q = i & 31;
        float4 v = make_float4(0.f, 0.f, 0.f, 0.f);
        if (row0g + row < NN) v = ((const float4*)x)[(size_t)(row0g + row) * 32 + q];
        uint4 t = make_uint4(f2tf32(v.x), f2tf32(v.y), f2tf32(v.z), f2tf32(v.w));
        *(uint4*)&As[row * SA + q * 4] = t;
    }
    // stage B = W [128][HF]
    for (int i = tid; i < 128 * (HF / 4); i += NT) {
        int row = i / (HF / 4), q = i % (HF / 4);
        float4 v = ((const float4*)W)[(size_t)row * (HF / 4) + q];
        uint4 t = make_uint4(f2tf32(v.x), f2tf32(v.y), f2tf32(v.z), f2tf32(v.w));
        *(uint4*)&Bs[row * SB + q * 4] = t;
    }
    __syncthreads();

    int wid = tid >> 5, lane = tid & 31;
    int g = lane >> 2, tig = lane & 3;
    int wr = wid / NCW, wc = wid % NCW;

    float acc[2][4][4];
#pragma unroll
    for (int mt = 0; mt < 2; mt++)
#pragma unroll
        for (int nt = 0; nt < 4; nt++)
#pragma unroll
            for (int q = 0; q < 4; q++) acc[mt][nt][q] = 0.f;

#pragma unroll
    for (int k0 = 0; k0 < 128; k0 += 8) {
        uint32_t a[2][4], b[4][2];
#pragma unroll
        for (int mt = 0; mt < 2; mt++) {
            const uint32_t* p = As + (wr * 32 + mt * 16 + g) * SA + k0 + tig;
            a[mt][0] = p[0];
            a[mt][1] = p[8 * SA];
            a[mt][2] = p[4];
            a[mt][3] = p[8 * SA + 4];
        }
#pragma unroll
        for (int nt = 0; nt < 4; nt++) {
            const uint32_t* p = Bs + (k0 + tig) * SB + wc * 32 + nt * 8 + g;
            b[nt][0] = p[0];
            b[nt][1] = p[4 * SB];
        }
#pragma unroll
        for (int mt = 0; mt < 2; mt++)
#pragma unroll
            for (int nt = 0; nt < 4; nt++) mma_tf32(acc[mt][nt], a[mt], b[nt]);
    }

    // writeback
#pragma unroll
    for (int mt = 0; mt < 2; mt++) {
        int r = row0g + wr * 32 + mt * 16 + g;
#pragma unroll
        for (int nt = 0; nt < 4; nt++) {
            int c = wc * 32 + nt * 8 + tig * 2;
            if (r < NN)
                *(float2*)&O[(size_t)r * HF + c] = make_float2(acc[mt][nt][0], acc[mt][nt][1]);
            if (r + 8 < NN)
                *(float2*)&O[(size_t)(r + 8) * HF + c] =
                    make_float2(acc[mt][nt][2], acc[mt][nt][3]);
        }
    }
}

// ---------------- el/er projections (+ zero BN stats for this layer) -------------
// NOTE: blockDim is 128; the zero loop MUST stride to cover all 320 entries
// (previous rounds zeroed only [0..127], leaving sumsq stale -> rel_err 0.51).
template <int HF, int FOUT>
__global__ void k_elr(const float* __restrict__ al, const float* __restrict__ ar) {
    if (blockIdx.x == 0) {
        for (int i = threadIdx.x; i < 320; i += blockDim.x) g_stat[i] = 0.f;
    }
    int idx = blockIdx.x * blockDim.x + threadIdx.x;
    if (idx >= NN * 4) return;
    int n = idx >> 2, h = idx & 3;
    const float* zp = g_z + (size_t)n * HF + h * FOUT;
    float sl = 0.f, sr = 0.f;
#pragma unroll 8
    for (int d = 0; d < FOUT; d++) {
        float v = zp[d];
        sl = fmaf(v, __ldg(al + h * FOUT + d), sl);
        sr = fmaf(v, __ldg(ar + h * FOUT + d), sr);
    }
    g_el[idx] = sl;
    g_er[idx] = sr;
}

// ---------------- edge softmax + aggregation (CSR, one warp per dst node) --------
template <int HF, int FOUT>
__global__ __launch_bounds__(256) void k_agg(const float* __restrict__ bc) {
    __shared__ float4 sm_ex[8][32];
    const unsigned FULL = 0xffffffffu;
    int wl = threadIdx.x >> 5;
    int lane = threadIdx.x & 31;
    int n = blockIdx.x * 8 + wl;
    if (n >= NN) return;
    int beg = g_rowptr[n], end = g_rowptr[n + 1];

    float4 er4 = *(const float4*)(g_er + 4 * n);

    // pass 1: per-head max over incoming edges
    float mx0 = -1e30f, mx1 = -1e30f, mx2 = -1e30f, mx3 = -1e30f;
    for (int e = beg + lane; e < end; e += 32) {
        int s = g_colsrc[e];
        float4 ev = *(const float4*)(g_el + 4 * s);
        float a;
        a = ev.x + er4.x; a = a > 0.f ? a : 0.2f * a; mx0 = fmaxf(mx0, a);
        a = ev.y + er4.y; a = a > 0.f ? a : 0.2f * a; mx1 = fmaxf(mx1, a);
        a = ev.z + er4.z; a = a > 0.f ? a : 0.2f * a; mx2 = fmaxf(mx2, a);
        a = ev.w + er4.w; a = a > 0.f ? a : 0.2f * a; mx3 = fmaxf(mx3, a);
    }
#pragma unroll
    for (int o = 16; o; o >>= 1) {
        mx0 = fmaxf(mx0, __shfl_xor_sync(FULL, mx0, o));
        mx1 = fmaxf(mx1, __shfl_xor_sync(FULL, mx1, o));
        mx2 = fmaxf(mx2, __shfl_xor_sync(FULL, mx2, o));
        mx3 = fmaxf(mx3, __shfl_xor_sync(FULL, mx3, o));
    }

    constexpr int J = HF / 32;
    float acc[J];
    int hj[J];
#pragma unroll
    for (int j = 0; j < J; j++) {
        acc[j] = 0.f;
        hj[j] = (lane + 32 * j) / FOUT;
    }

    // pass 2: lane-parallel exp -> shared; edge-serial weighted accumulate
    float4 sum4 = make_float4(0.f, 0.f, 0.f, 0.f);
    for (int base = beg; base < end; base += 32) {
        int mye = base + lane;
        int mys = 0;
        float4 ex4 = make_float4(0.f, 0.f, 0.f, 0.f);
        if (mye < end) {
            mys = g_colsrc[mye];
            float4 ev = *(const float4*)(g_el + 4 * mys);
            float a;
            a = ev.x + er4.x; a = a > 0.f ? a : 0.2f * a; ex4.x = __expf(a - mx0);
            a = ev.y + er4.y; a = a > 0.f ? a : 0.2f * a; ex4.y = __expf(a - mx1);
            a = ev.z + er4.z; a = a > 0.f ? a : 0.2f * a; ex4.z = __expf(a - mx2);
            a = ev.w + er4.w; a = a > 0.f ? a : 0.2f * a; ex4.w = __expf(a - mx3);
        }
        sum4.x += ex4.x; sum4.y += ex4.y; sum4.z += ex4.z; sum4.w += ex4.w;
        sm_ex[wl][lane] = ex4;
        __syncwarp();
        int cnt = min(32, end - base);
        for (int i = 0; i < cnt; i++) {
            int s = __shfl_sync(FULL, mys, i);
            float4 e4 = sm_ex[wl][i];
            const float* zp = g_z + (size_t)s * HF;
#pragma unroll
            for (int j = 0; j < J; j++) {
                float ev2 = (hj[j] == 0) ? e4.x : (hj[j] == 1) ? e4.y : (hj[j] == 2) ? e4.z : e4.w;
                acc[j] = fmaf(ev2, zp[lane + 32 * j], acc[j]);
            }
        }
        __syncwarp();
    }
#pragma unroll
    for (int o = 16; o; o >>= 1) {
        sum4.x += __shfl_xor_sync(FULL, sum4.x, o);
        sum4.y += __shfl_xor_sync(FULL, sum4.y, o);
        sum4.z += __shfl_xor_sync(FULL, sum4.z, o);
        sum4.w += __shfl_xor_sync(FULL, sum4.w, o);
    }
    float r0 = 1.f / (sum4.x == 0.f ? 1.f : sum4.x);
    float r1 = 1.f / (sum4.y == 0.f ? 1.f : sum4.y);
    float r2 = 1.f / (sum4.z == 0.f ? 1.f : sum4.z);
    float r3 = 1.f / (sum4.w == 0.f ? 1.f : sum4.w);

#pragma unroll
    for (int j = 0; j < J; j++) {
        float rv = (hj[j] == 0) ? r0 : (hj[j] == 1) ? r1 : (hj[j] == 2) ? r2 : r3;
        int c = lane + 32 * j;
        g_h[(size_t)n * HF + c] = acc[j] * rv + __ldg(bc + c) + g_lin[(size_t)n * HF + c];
    }
}

// ---------------- BatchNorm (over rows) + ReLU ----------------
__global__ void k_bnstats() {  // blockDim = 128 (one thread per column)
    int c = threadIdx.x;
    int G = gridDim.x;
    int per = (NN + G - 1) / G;
    int r0 = blockIdx.x * per;
    int r1 = min(NN, r0 + per);
    float s = 0.f, q = 0.f;
    for (int r = r0; r < r1; r++) {
        float v = g_h[(size_t)r * 128 + c];
        s += v;
        q = fmaf(v, v, q);
    }
    atomicAdd(&g_stat[c], s);
    atomicAdd(&g_stat[128 + c], q);
}

__global__ void k_bnapply(const float* __restrict__ g, const float* __restrict__ b) {
    int idx = blockIdx.x * blockDim.x + threadIdx.x;
    if (idx >= NN * 128) return;
    int c = idx & 127;
    float mu = g_stat[c] * (1.f / NN);
    float var = g_stat[128 + c] * (1.f / NN) - mu * mu;
    float y = (g_h[idx] - mu) * rsqrtf(var + 1e-5f) * __ldg(g + c) + __ldg(b + c);
    g_x[idx] = fmaxf(y, 0.f);
}

// ---------------- final head-mean + bias ----------------
__global__ void k_headmean(const float* __restrict__ bias, float* __restrict__ out) {
    int idx = blockIdx.x * blockDim.x + threadIdx.x;
    if (idx >= NN * 40) return;
    int n = idx / 40;
    int c = idx - 40 * n;
    const float* hp = g_h + (size_t)n * 160;
    float s = hp[c] + hp[40 + c] + hp[80 + c] + hp[120 + c];
    out[idx] = s * 0.25f + __ldg(bias + c);
}

// ---------------- host launch ----------------
extern "C" void kernel_launch(void* const* d_in, const int* in_sizes, int n_in,
                              void* d_out, int out_size) {
    const float* feat = (const float*)d_in[0];
    const int* src = (const int*)d_in[1];
    const int* dstp = (const int*)d_in[2];
    const float* Wc0 = (const float*)d_in[3];
    const float* al0 = (const float*)d_in[4];
    const float* ar0 = (const float*)d_in[5];
    const float* bc0 = (const float*)d_in[6];
    const float* Wl0 = (const float*)d_in[7];
    const float* Wc1 = (const float*)d_in[8];
    const float* al1 = (const float*)d_in[9];
    const float* ar1 = (const float*)d_in[10];
    const float* bc1 = (const float*)d_in[11];
    const float* Wl1 = (const float*)d_in[12];
    const float* Wc2 = (const float*)d_in[13];
    const float* al2 = (const float*)d_in[14];
    const float* ar2 = (const float*)d_in[15];
    const float* bc2 = (const float*)d_in[16];
    const float* Wl2 = (const float*)d_in[17];
    const float* g0 = (const float*)d_in[18];
    const float* b0 = (const float*)d_in[19];
    const float* g1 = (const float*)d_in[20];
    const float* b1 = (const float*)d_in[21];
    const float* bias_last = (const float*)d_in[22];
    float* out = (float*)d_out;

    float* xptr = nullptr;
    cudaGetSymbolAddress((void**)&xptr, g_x);

    const int SM128 = (128 * 132 + 128 * (128 + 4)) * 4;  // 135168
    const int SM160 = (128 * 132 + 128 * (160 + 4)) * 4;  // 151552
    cudaFuncSetAttribute(k_gemm_mma<128>, cudaFuncAttributeMaxDynamicSharedMemorySize, SM128);
    cudaFuncSetAttribute(k_gemm_mma<160>, cudaFuncAttributeMaxDynamicSharedMemorySize, SM160);

    // CSR build (dst-sorted)
    k_zero_cnt<<<(NN + 255) / 256, 256>>>();
    k_hist<<<(NE + 255) / 256, 256>>>(dstp);
    k_scan<<<1, 1024>>>();
    k_scatter<<<(NE + 255) / 256, 256>>>(src, dstp);

    const int MB = (NN + 127) / 128;  // 391 row tiles
    const int AB = (NN + 7) / 8;      // agg blocks (8 warps/block)

    // ---- layer 0 ----
    k_gemm_mma<128><<<dim3(MB, 2), 512, SM128>>>(feat, Wc0, Wl0);
    k_elr<128, 32><<<(NN * 4 + 127) / 128, 128>>>(al0, ar0);
    k_agg<128, 32><<<AB, 256>>>(bc0);
    k_bnstats<<<128, 128>>>();
    k_bnapply<<<(NN * 128 + 255) / 256, 256>>>(g0, b0);

    // ---- layer 1 ----
    k_gemm_mma<128><<<dim3(MB, 2), 512, SM128>>>(xptr, Wc1, Wl1);
    k_elr<128, 32><<<(NN * 4 + 127) / 128, 128>>>(al1, ar1);
    k_agg<128, 32><<<AB, 256>>>(bc1);
    k_bnstats<<<128, 128>>>();
    k_bnapply<<<(NN * 128 + 255) / 256, 256>>>(g1, b1);

    // ---- layer 2 ----
    k_gemm_mma<160><<<dim3(MB, 2), 640, SM160>>>(xptr, Wc2, Wl2);
    k_elr<160, 40><<<(NN * 4 + 127) / 128, 128>>>(al2, ar2);
    k_agg<160, 40><<<AB, 256>>>(bc2);
    k_headmean<<<(NN * 40 + 255) / 256, 256>>>(bias_last, out);
}

// round 9
// speedup vs baseline: 1.7936x; 1.2611x over previous
#include <cuda_runtime.h>
#include <cuda_bf16.h>
#include <math.h>
#include <stdint.h>

// Problem constants (fixed-shape problem)
#define NN 50000
#define NE 800000
// fin=128 always. HF (=H*fout) is 128,128,160. FOUT is 32,32,40. H=4.

// ---------------- scratch (device globals; no allocation allowed) ----------------
__device__ float g_z[NN * 160];     // z = x @ Wc      [N, HF]
__device__ float g_lin[NN * 160];   // lin = x @ Wl    [N, HF]
__device__ float g_h[NN * 160];     // layer output (pre-BN / pre-headmean)
__device__ float g_el[NN * 4];      // [N, H]
__device__ float g_er[NN * 4];      // [N, H]
__device__ int   g_rowptr[NN + 1];
__device__ int   g_cursor[NN];
__device__ int   g_cnt[NN];
__device__ int   g_colsrc[NE];      // CSR col: src node per (dst-sorted) edge
__device__ float g_stat[320];       // BN column sums [0,128) and sumsq [128,256)

// ---------------- CSR build ----------------
__global__ void k_zero_cnt() {
    int i = blockIdx.x * blockDim.x + threadIdx.x;
    if (i < NN) g_cnt[i] = 0;
}

__global__ void k_hist(const int* __restrict__ dst) {
    int e = blockIdx.x * blockDim.x + threadIdx.x;
    if (e < NE) atomicAdd(&g_cnt[dst[e]], 1);
}

// single-block exclusive scan of g_cnt -> g_rowptr (+ cursor copy)
__global__ void k_scan() {
    __shared__ int sm[1024];
    const int CH = 49;  // 1024*49 >= NN
    int t = threadIdx.x;
    int base = t * CH;
    int s = 0;
    for (int i = 0; i < CH; i++) {
        int idx = base + i;
        if (idx < NN) s += g_cnt[idx];
    }
    sm[t] = s;
    __syncthreads();
    for (int d = 1; d < 1024; d <<= 1) {
        int add = (t >= d) ? sm[t - d] : 0;
        __syncthreads();
        sm[t] += add;
        __syncthreads();
    }
    int run = sm[t] - s;
    for (int i = 0; i < CH; i++) {
        int idx = base + i;
        if (idx < NN) {
            g_rowptr[idx] = run;
            g_cursor[idx] = run;
            run += g_cnt[idx];
        }
    }
    if (t == 1023) g_rowptr[NN] = sm[1023];
}

__global__ void k_scatter(const int* __restrict__ src, const int* __restrict__ dst) {
    int e = blockIdx.x * blockDim.x + threadIdx.x;
    if (e < NE) {
        int p = atomicAdd(&g_cursor[dst[e]], 1);
        g_colsrc[p] = src[e];
    }
}

// ================= tf32 mma.sync helpers =================
__device__ __forceinline__ uint32_t f2tf32(float f) {
    uint32_t r;
    asm("cvt.rna.tf32.f32 %0, %1;" : "=r"(r) : "f"(f));
    return r;
}
__device__ __forceinline__ void mma_tf32(float* c, const uint32_t* a, const uint32_t* b) {
    asm volatile(
        "mma.sync.aligned.m16n8k8.row.col.f32.tf32.tf32.f32 "
        "{%0,%1,%2,%3}, {%4,%5,%6,%7}, {%8,%9}, {%0,%1,%2,%3};\n"
        : "+f"(c[0]), "+f"(c[1]), "+f"(c[2]), "+f"(c[3])
        : "r"(a[0]), "r"(a[1]), "r"(a[2]), "r"(a[3]), "r"(b[0]), "r"(b[1]));
}

// ========== fused dual-output GEMM + (optional) BN/ReLU input + el/er epilogue ====
// One CTA: 128-row tile, BOTH products z=x@Wc and lin=x@Wl, A staged once.
// 1024 threads = 32 warps: o = wid>>4 (0:Wc, 1:Wl), wr=(wid>>2)&3 (32-row band),
// wc = wid&3 (one head = FOUT cols). Warp tile 32 x FOUT (2 m16 x NT n8 tiles).
// K processed in 2 chunks of 64 (smem ~104/120 KB). If BN: input is
// relu(bn(g_h)) computed on the fly from g_stat + gamma/beta.
// Epilogue (o==0 warps): el/er = <z_head, al/ar> via in-register dot + shfl.
template <int HF, bool BN>
__global__ __launch_bounds__(1024, 1)
void k_gemm_fused(const float* __restrict__ x, const float* __restrict__ Wc,
                  const float* __restrict__ Wl, const float* __restrict__ al,
                  const float* __restrict__ ar, const float* __restrict__ gam,
                  const float* __restrict__ bet) {
    constexpr int FOUT = HF / 4;
    constexpr int NT = HF / 32;   // n8-tiles per warp (4 or 5)
    constexpr int SA = 68;        // A chunk row stride (words), K-chunk = 64
    constexpr int SB = HF + 4;    // B chunk row stride (words)
    const unsigned FULL = 0xffffffffu;
    extern __shared__ uint32_t smw[];
    float* sc = (float*)smw;             // [128] BN scale
    float* shf = sc + 128;               // [128] BN shift
    uint32_t* As = smw + 256;            // [128][SA]
    uint32_t* Bcs = As + 128 * SA;       // [64][SB]
    uint32_t* Bls = Bcs + 64 * SB;       // [64][SB]

    int tid = threadIdx.x;
    int row0g = blockIdx.x * 128;

    if (BN) {
        if (tid < 128) {
            float mu = g_stat[tid] * (1.f / NN);
            float var = g_stat[128 + tid] * (1.f / NN) - mu * mu;
            float rs = rsqrtf(var + 1e-5f) * gam[tid];
            sc[tid] = rs;
            shf[tid] = bet[tid] - mu * rs;
        }
        __syncthreads();
    }

    int wid = tid >> 5, lane = tid & 31;
    int g = lane >> 2, tig = lane & 3;
    int o = wid >> 4;
    int wr = (wid >> 2) & 3;
    int wc = wid & 3;
    const uint32_t* Bs = o ? Bls : Bcs;

    float acc[2][NT][4];
#pragma unroll
    for (int mt = 0; mt < 2; mt++)
#pragma unroll
        for (int nt = 0; nt < NT; nt++)
#pragma unroll
            for (int q = 0; q < 4; q++) acc[mt][nt][q] = 0.f;

#pragma unroll 1
    for (int kc = 0; kc < 2; kc++) {
        int k0 = kc * 64;
        // stage A chunk [128 rows x 64 cols] (tf32-rounded; BN+ReLU fused if BN)
#pragma unroll
        for (int ii = 0; ii < 2; ii++) {
            int i = ii * 1024 + tid;
            int row = i >> 4, q = i & 15;
            float4 v = make_float4(0.f, 0.f, 0.f, 0.f);
            if (row0g + row < NN) {
                v = ((const float4*)x)[(size_t)(row0g + row) * 32 + (k0 >> 2) + q];
                if (BN) {
                    int c = k0 + q * 4;
                    v.x = fmaxf(fmaf(v.x, sc[c + 0], shf[c + 0]), 0.f);
                    v.y = fmaxf(fmaf(v.y, sc[c + 1], shf[c + 1]), 0.f);
                    v.z = fmaxf(fmaf(v.z, sc[c + 2], shf[c + 2]), 0.f);
                    v.w = fmaxf(fmaf(v.w, sc[c + 3], shf[c + 3]), 0.f);
                }
            }
            uint4 t = make_uint4(f2tf32(v.x), f2tf32(v.y), f2tf32(v.z), f2tf32(v.w));
            *(uint4*)&As[row * SA + q * 4] = t;
        }
        // stage B chunks: Wc and Wl rows [k0, k0+64) x HF
        for (int i = tid; i < 2 * 64 * (HF / 4); i += 1024) {
            int m = i / (64 * (HF / 4));
            int r = (i / (HF / 4)) % 64;
            int qc = i % (HF / 4);
            const float* W = m ? Wl : Wc;
            float4 v = ((const float4*)W)[(size_t)(k0 + r) * (HF / 4) + qc];
            uint4 t = make_uint4(f2tf32(v.x), f2tf32(v.y), f2tf32(v.z), f2tf32(v.w));
            uint32_t* Bt = m ? Bls : Bcs;
            *(uint4*)&Bt[r * SB + qc * 4] = t;
        }
        __syncthreads();
        // compute 8 k-steps of 8
#pragma unroll
        for (int ks = 0; ks < 8; ks++) {
            int kk = ks * 8;
            uint32_t a[2][4], b[NT][2];
#pragma unroll
            for (int mt = 0; mt < 2; mt++) {
                const uint32_t* p = As + (wr * 32 + mt * 16 + g) * SA + kk + tig;
                a[mt][0] = p[0];
                a[mt][1] = p[8 * SA];
                a[mt][2] = p[4];
                a[mt][3] = p[8 * SA + 4];
            }
#pragma unroll
            for (int nt = 0; nt < NT; nt++) {
                const uint32_t* p = Bs + (kk + tig) * SB + wc * FOUT + nt * 8 + g;
                b[nt][0] = p[0];
                b[nt][1] = p[4 * SB];
            }
#pragma unroll
            for (int mt = 0; mt < 2; mt++)
#pragma unroll
                for (int nt = 0; nt < NT; nt++) mma_tf32(acc[mt][nt], a[mt], b[nt]);
        }
        __syncthreads();
    }

    // writeback
    float* O = o ? g_lin : g_z;
#pragma unroll
    for (int mt = 0; mt < 2; mt++) {
        int r = row0g + wr * 32 + mt * 16 + g;
#pragma unroll
        for (int nt = 0; nt < NT; nt++) {
            int c = wc * FOUT + nt * 8 + tig * 2;
            if (r < NN)
                *(float2*)&O[(size_t)r * HF + c] = make_float2(acc[mt][nt][0], acc[mt][nt][1]);
            if (r + 8 < NN)
                *(float2*)&O[(size_t)(r + 8) * HF + c] =
                    make_float2(acc[mt][nt][2], acc[mt][nt][3]);
        }
    }

    // epilogue: el/er for this warp's head (z warps only). head == wc.
    if (o == 0) {
        float sl0[2] = {0.f, 0.f}, sl1[2] = {0.f, 0.f};
        float sr0[2] = {0.f, 0.f}, sr1[2] = {0.f, 0.f};
#pragma unroll
        for (int nt = 0; nt < NT; nt++) {
            int cl = nt * 8 + tig * 2;
            float a0 = __ldg(al + wc * FOUT + cl);
            float a1 = __ldg(al + wc * FOUT + cl + 1);
            float r0v = __ldg(ar + wc * FOUT + cl);
            float r1v = __ldg(ar + wc * FOUT + cl + 1);
#pragma unroll
            for (int mt = 0; mt < 2; mt++) {
                sl0[mt] = fmaf(acc[mt][nt][0], a0, fmaf(acc[mt][nt][1], a1, sl0[mt]));
                sl1[mt] = fmaf(acc[mt][nt][2], a0, fmaf(acc[mt][nt][3], a1, sl1[mt]));
                sr0[mt] = fmaf(acc[mt][nt][0], r0v, fmaf(acc[mt][nt][1], r1v, sr0[mt]));
                sr1[mt] = fmaf(acc[mt][nt][2], r0v, fmaf(acc[mt][nt][3], r1v, sr1[mt]));
            }
        }
#pragma unroll
        for (int off = 1; off <= 2; off <<= 1) {
#pragma unroll
            for (int mt = 0; mt < 2; mt++) {
                sl0[mt] += __shfl_xor_sync(FULL, sl0[mt], off);
                sl1[mt] += __shfl_xor_sync(FULL, sl1[mt], off);
                sr0[mt] += __shfl_xor_sync(FULL, sr0[mt], off);
                sr1[mt] += __shfl_xor_sync(FULL, sr1[mt], off);
            }
        }
        if (tig == 0) {
#pragma unroll
            for (int mt = 0; mt < 2; mt++) {
                int r = row0g + wr * 32 + mt * 16 + g;
                if (r < NN) {
                    g_el[r * 4 + wc] = sl0[mt];
                    g_er[r * 4 + wc] = sr0[mt];
                }
                if (r + 8 < NN) {
                    g_el[(r + 8) * 4 + wc] = sl1[mt];
                    g_er[(r + 8) * 4 + wc] = sr1[mt];
                }
            }
        }
    }
}

// ---------------- edge softmax + aggregation (CSR, one warp per dst node) --------
// Block 0 also zeroes BN stats for the upcoming k_bnstats (safe: g_stat consumers
// — the previous gemm's staging — have already run; bnstats runs after this).
template <int HF, int FOUT>
__global__ __launch_bounds__(256) void k_agg(const float* __restrict__ bc) {
    __shared__ float4 sm_ex[8][32];
    const unsigned FULL = 0xffffffffu;
    if (blockIdx.x == 0 && threadIdx.x < 256) g_stat[threadIdx.x] = 0.f;
    int wl = threadIdx.x >> 5;
    int lane = threadIdx.x & 31;
    int n = blockIdx.x * 8 + wl;
    if (n >= NN) return;
    int beg = g_rowptr[n], end = g_rowptr[n + 1];

    float4 er4 = *(const float4*)(g_er + 4 * n);

    // pass 1: per-head max over incoming edges
    float mx0 = -1e30f, mx1 = -1e30f, mx2 = -1e30f, mx3 = -1e30f;
    for (int e = beg + lane; e < end; e += 32) {
        int s = g_colsrc[e];
        float4 ev = *(const float4*)(g_el + 4 * s);
        float a;
        a = ev.x + er4.x; a = a > 0.f ? a : 0.2f * a; mx0 = fmaxf(mx0, a);
        a = ev.y + er4.y; a = a > 0.f ? a : 0.2f * a; mx1 = fmaxf(mx1, a);
        a = ev.z + er4.z; a = a > 0.f ? a : 0.2f * a; mx2 = fmaxf(mx2, a);
        a = ev.w + er4.w; a = a > 0.f ? a : 0.2f * a; mx3 = fmaxf(mx3, a);
    }
#pragma unroll
    for (int o = 16; o; o >>= 1) {
        mx0 = fmaxf(mx0, __shfl_xor_sync(FULL, mx0, o));
        mx1 = fmaxf(mx1, __shfl_xor_sync(FULL, mx1, o));
        mx2 = fmaxf(mx2, __shfl_xor_sync(FULL, mx2, o));
        mx3 = fmaxf(mx3, __shfl_xor_sync(FULL, mx3, o));
    }

    constexpr int J = HF / 32;
    float acc[J];
    int hj[J];
#pragma unroll
    for (int j = 0; j < J; j++) {
        acc[j] = 0.f;
        hj[j] = (lane + 32 * j) / FOUT;
    }

    // pass 2: lane-parallel exp -> shared; edge-serial weighted accumulate
    float4 sum4 = make_float4(0.f, 0.f, 0.f, 0.f);
    for (int base = beg; base < end; base += 32) {
        int mye = base + lane;
        int mys = 0;
        float4 ex4 = make_float4(0.f, 0.f, 0.f, 0.f);
        if (mye < end) {
            mys = g_colsrc[mye];
            float4 ev = *(const float4*)(g_el + 4 * mys);
            float a;
            a = ev.x + er4.x; a = a > 0.f ? a : 0.2f * a; ex4.x = __expf(a - mx0);
            a = ev.y + er4.y; a = a > 0.f ? a : 0.2f * a; ex4.y = __expf(a - mx1);
            a = ev.z + er4.z; a = a > 0.f ? a : 0.2f * a; ex4.z = __expf(a - mx2);
            a = ev.w + er4.w; a = a > 0.f ? a : 0.2f * a; ex4.w = __expf(a - mx3);
        }
        sum4.x += ex4.x; sum4.y += ex4.y; sum4.z += ex4.z; sum4.w += ex4.w;
        sm_ex[wl][lane] = ex4;
        __syncwarp();
        int cnt = min(32, end - base);
        for (int i = 0; i < cnt; i++) {
            int s = __shfl_sync(FULL, mys, i);
            float4 e4 = sm_ex[wl][i];
            const float* zp = g_z + (size_t)s * HF;
#pragma unroll
            for (int j = 0; j < J; j++) {
                float ev2 = (hj[j] == 0) ? e4.x : (hj[j] == 1) ? e4.y : (hj[j] == 2) ? e4.z : e4.w;
                acc[j] = fmaf(ev2, zp[lane + 32 * j], acc[j]);
            }
        }
        __syncwarp();
    }
#pragma unroll
    for (int o = 16; o; o >>= 1) {
        sum4.x += __shfl_xor_sync(FULL, sum4.x, o);
        sum4.y += __shfl_xor_sync(FULL, sum4.y, o);
        sum4.z += __shfl_xor_sync(FULL, sum4.z, o);
        sum4.w += __shfl_xor_sync(FULL, sum4.w, o);
    }
    float r0 = 1.f / (sum4.x == 0.f ? 1.f : sum4.x);
    float r1 = 1.f / (sum4.y == 0.f ? 1.f : sum4.y);
    float r2 = 1.f / (sum4.z == 0.f ? 1.f : sum4.z);
    float r3 = 1.f / (sum4.w == 0.f ? 1.f : sum4.w);

#pragma unroll
    for (int j = 0; j < J; j++) {
        float rv = (hj[j] == 0) ? r0 : (hj[j] == 1) ? r1 : (hj[j] == 2) ? r2 : r3;
        int c = lane + 32 * j;
        g_h[(size_t)n * HF + c] = acc[j] * rv + __ldg(bc + c) + g_lin[(size_t)n * HF + c];
    }
}

// ---------------- BatchNorm column stats (sum, sumsq) ----------------
__global__ void k_bnstats() {  // blockDim = 128 (one thread per column)
    int c = threadIdx.x;
    int G = gridDim.x;
    int per = (NN + G - 1) / G;
    int r0 = blockIdx.x * per;
    int r1 = min(NN, r0 + per);
    float s = 0.f, q = 0.f;
    for (int r = r0; r < r1; r++) {
        float v = g_h[(size_t)r * 128 + c];
        s += v;
        q = fmaf(v, v, q);
    }
    atomicAdd(&g_stat[c], s);
    atomicAdd(&g_stat[128 + c], q);
}

// ---------------- final head-mean + bias ----------------
__global__ void k_headmean(const float* __restrict__ bias, float* __restrict__ out) {
    int idx = blockIdx.x * blockDim.x + threadIdx.x;
    if (idx >= NN * 40) return;
    int n = idx / 40;
    int c = idx - 40 * n;
    const float* hp = g_h + (size_t)n * 160;
    float s = hp[c] + hp[40 + c] + hp[80 + c] + hp[120 + c];
    out[idx] = s * 0.25f + __ldg(bias + c);
}

// ---------------- host launch ----------------
extern "C" void kernel_launch(void* const* d_in, const int* in_sizes, int n_in,
                              void* d_out, int out_size) {
    const float* feat = (const float*)d_in[0];
    const int* src = (const int*)d_in[1];
    const int* dstp = (const int*)d_in[2];
    const float* Wc0 = (const float*)d_in[3];
    const float* al0 = (const float*)d_in[4];
    const float* ar0 = (const float*)d_in[5];
    const float* bc0 = (const float*)d_in[6];
    const float* Wl0 = (const float*)d_in[7];
    const float* Wc1 = (const float*)d_in[8];
    const float* al1 = (const float*)d_in[9];
    const float* ar1 = (const float*)d_in[10];
    const float* bc1 = (const float*)d_in[11];
    const float* Wl1 = (const float*)d_in[12];
    const float* Wc2 = (const float*)d_in[13];
    const float* al2 = (const float*)d_in[14];
    const float* ar2 = (const float*)d_in[15];
    const float* bc2 = (const float*)d_in[16];
    const float* Wl2 = (const float*)d_in[17];
    const float* g0 = (const float*)d_in[18];
    const float* b0 = (const float*)d_in[19];
    const float* g1 = (const float*)d_in[20];
    const float* b1 = (const float*)d_in[21];
    const float* bias_last = (const float*)d_in[22];
    float* out = (float*)d_out;

    float* hptr = nullptr;
    cudaGetSymbolAddress((void**)&hptr, g_h);

    const int SMF128 = (256 + 128 * 68 + 2 * 64 * 132) * 4;  // 103,424
    const int SMF160 = (256 + 128 * 68 + 2 * 64 * 164) * 4;  // 119,808
    cudaFuncSetAttribute(k_gemm_fused<128, false>, cudaFuncAttributeMaxDynamicSharedMemorySize, SMF128);
    cudaFuncSetAttribute(k_gemm_fused<128, true>, cudaFuncAttributeMaxDynamicSharedMemorySize, SMF128);
    cudaFuncSetAttribute(k_gemm_fused<160, true>, cudaFuncAttributeMaxDynamicSharedMemorySize, SMF160);

    // CSR build (dst-sorted)
    k_zero_cnt<<<(NN + 255) / 256, 256>>>();
    k_hist<<<(NE + 255) / 256, 256>>>(dstp);
    k_scan<<<1, 1024>>>();
    k_scatter<<<(NE + 255) / 256, 256>>>(src, dstp);

    const int MB = (NN + 127) / 128;  // 391 row tiles
    const int AB = (NN + 7) / 8;      // agg blocks (8 warps/block)

    // ---- layer 0 ----
    k_gemm_fused<128, false><<<MB, 1024, SMF128>>>(feat, Wc0, Wl0, al0, ar0, nullptr, nullptr);
    k_agg<128, 32><<<AB, 256>>>(bc0);
    k_bnstats<<<128, 128>>>();

    // ---- layer 1 (BN of layer-0 output fused into GEMM staging) ----
    k_gemm_fused<128, true><<<MB, 1024, SMF128>>>(hptr, Wc1, Wl1, al1, ar1, g0, b0);
    k_agg<128, 32><<<AB, 256>>>(bc1);
    k_bnstats<<<128, 128>>>();

    // ---- layer 2 (BN of layer-1 output fused into GEMM staging) ----
    k_gemm_fused<160, true><<<MB, 1024, SMF160>>>(hptr, Wc2, Wl2, al2, ar2, g1, b1);
    k_agg<160, 40><<<AB, 256>>>(bc2);
    k_headmean<<<(NN * 40 + 255) / 256, 256>>>(bias_last, out);
}